// round 1
// baseline (speedup 1.0000x reference)
#include <cuda_runtime.h>
#include <math_constants.h>

#define NLAT  256
#define NLON  512
#define LMAX  50
#define MMAX  50
#define BATCH 2
#define NPTS  2048
#define MGRID (NLAT*NLON)

#define PI_F 3.14159265358979323846f

// scratch (no cudaMalloc allowed)
__device__ float4 g_cand[BATCH][NPTS];            // (phi, theta-pi, (x^2+y^2)/2, rho)
__device__ float  g_interp[BATCH][MGRID];         // interpolated grid
__device__ float  g_xf[BATCH][MMAX][NLAT];        // DFT real modes, transposed for einsum

// ---------------------------------------------------------------------------
// Kernel 1: to_spherical + candidate preprocessing
// ---------------------------------------------------------------------------
__global__ void prep_kernel(const float* __restrict__ pred) {
    int t = blockIdx.x * blockDim.x + threadIdx.x;
    if (t >= BATCH * NPTS) return;
    float x = pred[3*t+0], y = pred[3*t+1], z = pred[3*t+2];
    float rho = sqrtf(x*x + y*y + z*z);
    float phi = atan2f(y, x);
    float th  = acosf(z / rho) - PI_F;
    float c   = 0.5f * (phi*phi + th*th);
    g_cand[t >> 11][t & (NPTS-1)] = make_float4(phi, th, c, rho);
}

// ---------------------------------------------------------------------------
// Kernel 2: brute-force 3-NN + distance-weighted interpolation
// ranking key: d' = c - sx*gx - sy*gy   (monotone with true d^2 per grid pt)
// ---------------------------------------------------------------------------
#define KNN_G 4
#define KNN_T 256

__global__ void __launch_bounds__(KNN_T) knn_kernel() {
    __shared__ float4 sc[NPTS];
    int b = blockIdx.y;
    for (int i = threadIdx.x; i < NPTS; i += KNN_T)
        sc[i] = g_cand[b][i];
    __syncthreads();

    float ngx[KNN_G], ngy[KNN_G];
    float b0[KNN_G], b1[KNN_G], b2[KNN_G];
    int   i0[KNN_G], i1[KNN_G], i2[KNN_G];
    const int base = blockIdx.x * (KNN_T * KNN_G) + threadIdx.x;
    const float SCALE = PI_F / NLAT;

#pragma unroll
    for (int g = 0; g < KNN_G; g++) {
        int m  = base + g * KNN_T;
        int gi = m >> 9;              // lat index
        int gj = m & (NLON - 1);      // lon index (maps to gy = (gj-256)*pi/256)
        ngx[g] = -(float)gi * SCALE;
        ngy[g] = -(float)(gj - NLAT) * SCALE;
        b0[g] = b1[g] = b2[g] = CUDART_INF_F;
        i0[g] = i1[g] = i2[g] = 0;
    }

    for (int n = 0; n < NPTS; n++) {
        float4 cd = sc[n];
#pragma unroll
        for (int g = 0; g < KNN_G; g++) {
            float d = fmaf(cd.x, ngx[g], fmaf(cd.y, ngy[g], cd.z));
            if (d < b2[g]) {                       // rare
                if (d < b1[g]) {
                    b2[g] = b1[g]; i2[g] = i1[g];
                    if (d < b0[g]) { b1[g] = b0[g]; i1[g] = i0[g]; b0[g] = d; i0[g] = n; }
                    else           { b1[g] = d;     i1[g] = n; }
                } else {
                    b2[g] = d; i2[g] = n;
                }
            }
        }
    }

#pragma unroll
    for (int g = 0; g < KNN_G; g++) {
        int m = base + g * KNN_T;
        float gx = -ngx[g], gy = -ngy[g];
        float4 w0 = sc[i0[g]], w1 = sc[i1[g]], w2 = sc[i2[g]];
        float dx0 = w0.x - gx, dy0 = w0.y - gy;
        float dx1 = w1.x - gx, dy1 = w1.y - gy;
        float dx2 = w2.x - gx, dy2 = w2.y - gy;
        float t0 = sqrtf(dx0*dx0 + dy0*dy0);
        float t1 = sqrtf(dx1*dx1 + dy1*dy1);
        float t2 = sqrtf(dx2*dx2 + dy2*dy2);
        float s  = t0 + t1 + t2;
        // weights proportional to distance (matches reference source)
        float v  = (w0.w*t0 + w1.w*t1 + w2.w*t2) / s;
        g_interp[b][m] = v;
    }
}

// ---------------------------------------------------------------------------
// Kernel 3: direct real DFT over longitude, first MMAX cosine modes
// xf[b,m,k] = (1/NLON) * sum_j interp[b,k,j] * cos(2*pi*m*j/NLON)
// ---------------------------------------------------------------------------
__global__ void __launch_bounds__(64) dft_kernel() {
    __shared__ float row[NLON];
    __shared__ float ctab[NLON];
    int b = blockIdx.x >> 8;
    int k = blockIdx.x & (NLAT - 1);
    const float* rp = &g_interp[b][k * NLON];
    for (int t = threadIdx.x; t < NLON; t += 64) {
        row[t]  = rp[t];
        ctab[t] = cospif((float)t * (2.0f / NLON));   // cos(2*pi*t/NLON)
    }
    __syncthreads();
    int m = threadIdx.x;
    if (m < MMAX) {
        float acc = 0.f;
#pragma unroll 8
        for (int j = 0; j < NLON; j++)
            acc = fmaf(row[j], ctab[(m * j) & (NLON - 1)], acc);
        g_xf[b][m][k] = acc * (1.0f / NLON);
    }
}

// ---------------------------------------------------------------------------
// Kernel 4: Legendre contraction + weighted MSE, single block, deterministic
// coeffs[b,l,m] = 2*pi * sum_k xf[b,m,k] * pct[m,l,k]
// loss = mean_b sum_{l,m} (coeffs - target)^2 * rect[l]
// ---------------------------------------------------------------------------
__global__ void __launch_bounds__(1024) loss_kernel(const float* __restrict__ target,
                                                    const float* __restrict__ pct,
                                                    const float* __restrict__ rect,
                                                    float* __restrict__ out) {
    float acc = 0.f;
    for (int t = threadIdx.x; t < BATCH * LMAX * MMAX; t += 1024) {
        int b = t / (LMAX * MMAX);
        int r = t - b * (LMAX * MMAX);
        int l = r / MMAX;
        int m = r - l * MMAX;
        const float* pw = pct + (m * LMAX + l) * NLAT;
        const float* xw = &g_xf[b][m][0];
        float dot = 0.f;
#pragma unroll 8
        for (int k = 0; k < NLAT; k++)
            dot = fmaf(xw[k], pw[k], dot);
        float coeff = 6.2831853071795864f * dot;
        float diff  = coeff - target[t];
        acc = fmaf(diff * diff, rect[l], acc);
    }
    __shared__ float red[32];
#pragma unroll
    for (int o = 16; o; o >>= 1) acc += __shfl_down_sync(0xffffffffu, acc, o);
    if ((threadIdx.x & 31) == 0) red[threadIdx.x >> 5] = acc;
    __syncthreads();
    if (threadIdx.x < 32) {
        float v = red[threadIdx.x];
#pragma unroll
        for (int o = 16; o; o >>= 1) v += __shfl_down_sync(0xffffffffu, v, o);
        if (threadIdx.x == 0) out[0] = v * (1.0f / BATCH);
    }
}

// ---------------------------------------------------------------------------
extern "C" void kernel_launch(void* const* d_in, const int* in_sizes, int n_in,
                              void* d_out, int out_size) {
    const float* pred   = (const float*)d_in[0];
    const float* target = (const float*)d_in[1];
    // d_in[2] = grid (implicit, recomputed on the fly)
    const float* pct    = (const float*)d_in[3];
    const float* rect   = (const float*)d_in[4];
    float* out = (float*)d_out;

    prep_kernel<<<(BATCH * NPTS + 255) / 256, 256>>>(pred);
    dim3 kg(MGRID / (KNN_T * KNN_G), BATCH);
    knn_kernel<<<kg, KNN_T>>>();
    dft_kernel<<<BATCH * NLAT, 64>>>();
    loss_kernel<<<1, 1024>>>(target, pct, rect, out);
}

// round 4
// speedup vs baseline: 1.0964x; 1.0964x over previous
#include <cuda_runtime.h>

#define NLAT  256
#define NLON  512
#define LMAX  50
#define MMAX  50
#define BATCH 2
#define NPTS  2048
#define MGRID (NLAT*NLON)

#define NX 64
#define NY 32
#define NCELL (NX*NY)

#define PI_F 3.14159265358979323846f
#define HX (2.0f*PI_F/(float)NX)   /* = pi/32 */
#define HY (PI_F/(float)NY)        /* = pi/32 */
#define X0F (-PI_F)
#define Y0F (-PI_F)

// -------- scratch (no cudaMalloc allowed) ----------------------------------
__device__ float4 g_cand[BATCH][NPTS];     // (phi, theta-pi, rho, index-bits)
__device__ float4 g_sorted[BATCH][NPTS];   // cell-sorted copy of g_cand
__device__ int    g_cellCnt[BATCH][NCELL];
__device__ int    g_cellFill[BATCH][NCELL];
__device__ int    g_cellStart[BATCH][NCELL + 1];
__device__ float  g_interp[BATCH][MGRID];
__device__ float  g_xf[BATCH][MMAX][NLAT];

// ---------------------------------------------------------------------------
__global__ void zero_kernel() {
    int t = blockIdx.x * blockDim.x + threadIdx.x;
    if (t < BATCH * NCELL) {
        ((int*)g_cellCnt)[t]  = 0;
        ((int*)g_cellFill)[t] = 0;
    }
}

// to_spherical + histogram of cell occupancy
__global__ void prep_kernel(const float* __restrict__ pred) {
    int t = blockIdx.x * blockDim.x + threadIdx.x;
    if (t >= BATCH * NPTS) return;
    float x = pred[3*t+0], y = pred[3*t+1], z = pred[3*t+2];
    float rho = sqrtf(x*x + y*y + z*z);
    float phi = atan2f(y, x);
    float th  = acosf(z / rho) - PI_F;
    int b = t >> 11, n = t & (NPTS - 1);
    g_cand[b][n] = make_float4(phi, th, rho, __uint_as_float((unsigned)n));
    int ci = min(max((int)floorf((phi - X0F) / HX), 0), NX - 1);
    int cj = min(max((int)floorf((th  - Y0F) / HY), 0), NY - 1);
    atomicAdd(&g_cellCnt[b][cj * NX + ci], 1);
}

// exclusive prefix over 2048 cells (one block per batch, 1024 threads)
__global__ void __launch_bounds__(1024) scan_kernel() {
    __shared__ int s[NCELL];
    int b = blockIdx.x;
    int i0 = threadIdx.x, i1 = threadIdx.x + 1024;
    s[i0] = g_cellCnt[b][i0];
    s[i1] = g_cellCnt[b][i1];
    __syncthreads();
    for (int off = 1; off < NCELL; off <<= 1) {
        int v0 = (i0 >= off) ? s[i0 - off] : 0;
        int v1 = (i1 >= off) ? s[i1 - off] : 0;
        __syncthreads();
        s[i0] += v0; s[i1] += v1;
        __syncthreads();
    }
    g_cellStart[b][i0 + 1] = s[i0];
    g_cellStart[b][i1 + 1] = s[i1];
    if (i0 == 0) g_cellStart[b][0] = 0;
}

__global__ void scatter_kernel() {
    int t = blockIdx.x * blockDim.x + threadIdx.x;
    if (t >= BATCH * NPTS) return;
    int b = t >> 11, n = t & (NPTS - 1);
    float4 c = g_cand[b][n];
    int ci = min(max((int)floorf((c.x - X0F) / HX), 0), NX - 1);
    int cj = min(max((int)floorf((c.y - Y0F) / HY), 0), NY - 1);
    int cell = cj * NX + ci;
    int pos = g_cellStart[b][cell] + atomicAdd(&g_cellFill[b][cell], 1);
    g_sorted[b][pos] = c;
}

// ---------------------------------------------------------------------------
// 3-NN via expanding-ring cell search, branchless packed top-3.
// key = float(d^2) with low 11 mantissa bits replaced by the candidate index:
// positive-float ordering == uint ordering, distinct indices -> strict order.
// ---------------------------------------------------------------------------
__device__ __forceinline__ void scan_range(const float4* __restrict__ SP,
                                           int s, int e, float qx, float qy,
                                           float& b0, float& b1, float& b2) {
    for (int k = s; k < e; k++) {
        float4 p = SP[k];
        float dx = p.x - qx, dy = p.y - qy;
        float d2 = fmaf(dx, dx, dy * dy);
        unsigned key = (__float_as_uint(d2) & 0xFFFFF800u) | __float_as_uint(p.w);
        float kf = __uint_as_float(key);
        float t0 = fmaxf(b0, kf); b0 = fminf(b0, kf);
        float t1 = fmaxf(b1, t0); b1 = fminf(b1, t0);
        b2 = fminf(b2, t1);
    }
}

__global__ void __launch_bounds__(256) knn_kernel() {
    int t = blockIdx.x * blockDim.x + threadIdx.x;   // 0 .. BATCH*MGRID-1
    int b = t >> 17;
    int m = t & (MGRID - 1);
    int gi = m >> 9;
    int gj = m & (NLON - 1);
    const float GS = PI_F / (float)NLAT;
    float qx = (float)gi * GS;             // [0, pi)
    float qy = (float)(gj - NLAT) * GS;    // [-pi, pi)

    int ci = min(max((int)floorf((qx - X0F) / HX), 0), NX - 1);
    int cj = min(max((int)floorf((qy - Y0F) / HY), 0), NY - 1);
    const int*    CS = g_cellStart[b];
    const float4* SP = g_sorted[b];

    float b0 = __uint_as_float(0x7F800000u), b1 = b0, b2 = b0;

    float fx = qx - (X0F + ci * HX);       // offset inside center cell (x)
    float fy = qy - (Y0F + cj * HY);       // may exceed HY if qy > 0 (above box)
    float gy = fmaxf(qy, 0.0f);            // y-gap from query to candidate box
    float gy2 = gy * gy;

    for (int r = 0; ; r++) {
        int ilo = max(ci - r, 0), ihi = min(ci + r, NX - 1);
        int jlo = cj - r, jhi = cj + r;
        if (jlo >= 0) {                                   // bottom row of ring
            scan_range(SP, CS[jlo * NX + ilo], CS[jlo * NX + ihi + 1], qx, qy, b0, b1, b2);
        }
        if (r > 0 && jhi <= NY - 1) {                     // top row of ring
            scan_range(SP, CS[jhi * NX + ilo], CS[jhi * NX + ihi + 1], qx, qy, b0, b1, b2);
        }
        if (r > 0) {                                      // side columns
            int ja = max(jlo + 1, 0), jb = min(jhi - 1, NY - 1);
            for (int j = ja; j <= jb; j++) {
                if (ci - r >= 0) {
                    int c = j * NX + (ci - r);
                    scan_range(SP, CS[c], CS[c + 1], qx, qy, b0, b1, b2);
                }
                if (ci + r <= NX - 1) {
                    int c = j * NX + (ci + r);
                    scan_range(SP, CS[c], CS[c + 1], qx, qy, b0, b1, b2);
                }
            }
        }
        // lower bound on any unscanned candidate's distance^2
        float lb2 = 3.0e38f;
        bool any = false;
        if (ci - r > 0)      { float s = fx + r * HX;        lb2 = fminf(lb2, fmaf(s, s, gy2)); any = true; }
        if (ci + r < NX - 1) { float s = (HX - fx) + r * HX; lb2 = fminf(lb2, fmaf(s, s, gy2)); any = true; }
        if (cj - r > 0)      { float s = fy + r * HY;        lb2 = fminf(lb2, s * s);           any = true; }
        if (cj + r < NY - 1) { float s = (HY - fy) + r * HY; lb2 = fminf(lb2, s * s);           any = true; }
        if (!any) break;                               // whole box scanned
        if (lb2 > b2 * 1.0009765625f) break;           // slack > packing error
        if (r >= 64) break;                            // safety net
    }

    // exact distances / weights for the 3 winners (deterministic winner set)
    unsigned n0 = __float_as_uint(b0) & 0x7FFu;
    unsigned n1 = __float_as_uint(b1) & 0x7FFu;
    unsigned n2 = __float_as_uint(b2) & 0x7FFu;
    float4 w0 = g_cand[b][n0], w1 = g_cand[b][n1], w2 = g_cand[b][n2];
    float dx0 = w0.x - qx, dy0 = w0.y - qy;
    float dx1 = w1.x - qx, dy1 = w1.y - qy;
    float dx2 = w2.x - qx, dy2 = w2.y - qy;
    float t0 = sqrtf(dx0*dx0 + dy0*dy0);
    float t1 = sqrtf(dx1*dx1 + dy1*dy1);
    float t2 = sqrtf(dx2*dx2 + dy2*dy2);
    float s  = t0 + t1 + t2;
    g_interp[b][m] = (w0.z*t0 + w1.z*t1 + w2.z*t2) / s;   // weights prop. to distance
}

// ---------------------------------------------------------------------------
// direct real DFT over longitude, first MMAX cosine modes
// ---------------------------------------------------------------------------
__global__ void __launch_bounds__(64) dft_kernel() {
    __shared__ float row[NLON];
    __shared__ float ctab[NLON];
    int b = blockIdx.x >> 8;
    int k = blockIdx.x & (NLAT - 1);
    const float* rp = &g_interp[b][k * NLON];
    for (int t = threadIdx.x; t < NLON; t += 64) {
        row[t]  = rp[t];
        ctab[t] = cospif((float)t * (2.0f / NLON));
    }
    __syncthreads();
    int m = threadIdx.x;
    if (m < MMAX) {
        float acc = 0.f;
#pragma unroll 8
        for (int j = 0; j < NLON; j++)
            acc = fmaf(row[j], ctab[(m * j) & (NLON - 1)], acc);
        g_xf[b][m][k] = acc * (1.0f / NLON);
    }
}

// ---------------------------------------------------------------------------
// Legendre contraction + weighted MSE, single block, deterministic
// ---------------------------------------------------------------------------
__global__ void __launch_bounds__(1024) loss_kernel(const float* __restrict__ target,
                                                    const float* __restrict__ pct,
                                                    const float* __restrict__ rect,
                                                    float* __restrict__ out) {
    float acc = 0.f;
    for (int t = threadIdx.x; t < BATCH * LMAX * MMAX; t += 1024) {
        int b = t / (LMAX * MMAX);
        int r = t - b * (LMAX * MMAX);
        int l = r / MMAX;
        int m = r - l * MMAX;
        const float* pw = pct + (m * LMAX + l) * NLAT;
        const float* xw = &g_xf[b][m][0];
        float dot = 0.f;
#pragma unroll 8
        for (int k = 0; k < NLAT; k++)
            dot = fmaf(xw[k], pw[k], dot);
        float coeff = 6.2831853071795864f * dot;
        float diff  = coeff - target[t];
        acc = fmaf(diff * diff, rect[l], acc);
    }
    __shared__ float red[32];
#pragma unroll
    for (int o = 16; o; o >>= 1) acc += __shfl_down_sync(0xffffffffu, acc, o);
    if ((threadIdx.x & 31) == 0) red[threadIdx.x >> 5] = acc;
    __syncthreads();
    if (threadIdx.x < 32) {
        float v = red[threadIdx.x];
#pragma unroll
        for (int o = 16; o; o >>= 1) v += __shfl_down_sync(0xffffffffu, v, o);
        if (threadIdx.x == 0) out[0] = v * (1.0f / BATCH);
    }
}

// ---------------------------------------------------------------------------
extern "C" void kernel_launch(void* const* d_in, const int* in_sizes, int n_in,
                              void* d_out, int out_size) {
    const float* pred   = (const float*)d_in[0];
    const float* target = (const float*)d_in[1];
    // d_in[2] = grid (recomputed analytically on the fly)
    const float* pct    = (const float*)d_in[3];
    const float* rect   = (const float*)d_in[4];
    float* out = (float*)d_out;

    zero_kernel<<<(BATCH * NCELL + 255) / 256, 256>>>();
    prep_kernel<<<(BATCH * NPTS + 255) / 256, 256>>>(pred);
    scan_kernel<<<BATCH, 1024>>>();
    scatter_kernel<<<(BATCH * NPTS + 255) / 256, 256>>>();
    knn_kernel<<<(BATCH * MGRID) / 256, 256>>>();
    dft_kernel<<<BATCH * NLAT, 64>>>();
    loss_kernel<<<1, 1024>>>(target, pct, rect, out);
}